// round 2
// baseline (speedup 1.0000x reference)
#include <cuda_runtime.h>

static constexpr int B = 8;
static constexpr int C = 128;
static constexpr int N = 3136;                  // 56*56
static constexpr size_t NN = (size_t)N * N;
static constexpr size_t XE = (size_t)B * C * N;

__device__ float  g_E[(size_t)B * NN];          // energy -> raw (pre-softmax) kept raw
__device__ float2 g_MS[(size_t)B * N];          // per-row (max, 1/sum)

// ---------------------------------------------------------------------------
// K1: E = V^T V, diagonal zeroed. 128x128 tile, 8x8 microtile, symmetry:
// only tj>=ti computed; mirror written via 32-row smem transpose slabs.
// grid (25,25,B), block 256 (16x16).
// ---------------------------------------------------------------------------
__global__ __launch_bounds__(256, 2) void k1_gram(const float* __restrict__ x) {
    const int ti = blockIdx.x, tj = blockIdx.y, b = blockIdx.z;
    if (tj < ti) return;

    __shared__ float As[8][128];
    __shared__ float Bsh[8][128];
    __shared__ float T[32][129];

    const float* V = x + (size_t)b * C * N;
    const int tid = threadIdx.x;
    const int tx = tid & 15, ty = tid >> 4;
    const int i0 = ti * 128, j0 = tj * 128;

    float acc[8][8];
    #pragma unroll
    for (int r = 0; r < 8; r++)
        #pragma unroll
        for (int s = 0; s < 8; s++) acc[r][s] = 0.0f;

    for (int c0 = 0; c0 < C; c0 += 8) {
        #pragma unroll
        for (int r = 0; r < 4; r++) {
            int e = tid + r * 256;
            int cc = e >> 7, col = e & 127;
            const float* row = V + (size_t)(c0 + cc) * N;
            As[cc][col]  = row[min(i0 + col, N - 1)];
            Bsh[cc][col] = row[min(j0 + col, N - 1)];
        }
        __syncthreads();

        #pragma unroll
        for (int cc = 0; cc < 8; cc++) {
            float4 a0 = *(const float4*)&As[cc][ty * 4];
            float4 a1 = *(const float4*)&As[cc][ty * 4 + 64];
            float4 b0 = *(const float4*)&Bsh[cc][tx * 4];
            float4 b1 = *(const float4*)&Bsh[cc][tx * 4 + 64];
            float a[8] = {a0.x, a0.y, a0.z, a0.w, a1.x, a1.y, a1.z, a1.w};
            float bb[8] = {b0.x, b0.y, b0.z, b0.w, b1.x, b1.y, b1.z, b1.w};
            #pragma unroll
            for (int r = 0; r < 8; r++)
                #pragma unroll
                for (int s = 0; s < 8; s++)
                    acc[r][s] += a[r] * bb[s];
        }
        __syncthreads();
    }

    float* E = g_E + (size_t)b * NN;

    // Main tile store (float4, diagonal fixed only in diagonal blocks)
    #pragma unroll
    for (int rh = 0; rh < 2; rh++)
        #pragma unroll
        for (int rr = 0; rr < 4; rr++) {
            int i = i0 + ty * 4 + rh * 64 + rr;
            if (i >= N) continue;
            #pragma unroll
            for (int sh = 0; sh < 2; sh++) {
                int j = j0 + tx * 4 + sh * 64;
                if (j >= N) continue;
                float4 v;
                v.x = acc[rh * 4 + rr][sh * 4 + 0];
                v.y = acc[rh * 4 + rr][sh * 4 + 1];
                v.z = acc[rh * 4 + rr][sh * 4 + 2];
                v.w = acc[rh * 4 + rr][sh * 4 + 3];
                if (ti == tj) {
                    int d = i - j;
                    if (d >= 0 && d < 4) ((float*)&v)[d] = 0.0f;
                }
                *(float4*)&E[(size_t)i * N + j] = v;
            }
        }

    if (ti != tj) {
        // Mirror tile E[j][i] via 4 slabs of 32 mirror-rows
        #pragma unroll
        for (int p = 0; p < 4; p++) {
            __syncthreads();
            int sh = p >> 1;
            int want_hi = p & 1;
            if ((tx >> 3) == want_hi) {
                int txl = tx & 7;
                #pragma unroll
                for (int s = 0; s < 4; s++) {
                    int lc = txl * 4 + s;
                    #pragma unroll
                    for (int rh = 0; rh < 2; rh++)
                        #pragma unroll
                        for (int rr = 0; rr < 4; rr++)
                            T[lc][ty * 4 + rh * 64 + rr] = acc[rh * 4 + rr][sh * 4 + s];
                }
            }
            __syncthreads();
            #pragma unroll
            for (int q = 0; q < 16; q++) {
                int e = tid + q * 256;
                int lr = e >> 7, lcx = e & 127;
                int jr = j0 + p * 32 + lr;
                int ic = i0 + lcx;
                if (jr < N && ic < N)
                    E[(size_t)jr * N + ic] = T[lr][lcx];
            }
        }
    }
}

// ---------------------------------------------------------------------------
// K2: per-row (max, 1/sum(exp)) only — no E write-back. grid (N, B), 256 thr.
// ---------------------------------------------------------------------------
__global__ __launch_bounds__(256) void k2_rowstats() {
    const int row = blockIdx.x, b = blockIdx.y;
    const float* E = g_E + (size_t)b * NN + (size_t)row * N;

    __shared__ float sv[N];
    __shared__ float red[256];
    const int tid = threadIdx.x;

    float m = -1e30f;
    for (int j = tid; j < N; j += 256) {
        float v = E[j];
        sv[j] = v;
        m = fmaxf(m, v);
    }
    red[tid] = m;
    __syncthreads();
    #pragma unroll
    for (int s = 128; s > 0; s >>= 1) {
        if (tid < s) red[tid] = fmaxf(red[tid], red[tid + s]);
        __syncthreads();
    }
    m = red[0];
    __syncthreads();

    float sum = 0.0f;
    for (int j = tid; j < N; j += 256)
        sum += __expf(sv[j] - m);
    red[tid] = sum;
    __syncthreads();
    #pragma unroll
    for (int s = 128; s > 0; s >>= 1) {
        if (tid < s) red[tid] += red[tid + s];
        __syncthreads();
    }
    if (tid == 0) g_MS[(size_t)b * N + row] = make_float2(m, 1.0f / red[0]);
}

// ---------------------------------------------------------------------------
// K3: out[c,j] = sum_i V[c,i] * softmax(E)[i,j], softmax applied on the fly.
// 128(c) x 64(j) tile, 8x8 microtile, 128 threads. grid (49, B).
// Fused relu + y = gamma*out + x epilogue.
// ---------------------------------------------------------------------------
__global__ __launch_bounds__(128, 4) void k3_out(const float* __restrict__ x,
                                                 const float* __restrict__ gamma_p,
                                                 float* __restrict__ y_out,
                                                 float* __restrict__ o_out) {
    const int b = blockIdx.y;
    const int j0 = blockIdx.x * 64;
    const float* V = x + (size_t)b * C * N;
    const float* E = g_E + (size_t)b * NN;
    const float2* MS = g_MS + (size_t)b * N;

    __shared__ float Vs[16][132];   // [kk][c], padded
    __shared__ float As2[16][64];   // [kk][jj] attention tile

    const int tid = threadIdx.x;
    const int tx = tid & 7, ty = tid >> 3;

    float acc[8][8];
    #pragma unroll
    for (int r = 0; r < 8; r++)
        #pragma unroll
        for (int s = 0; s < 8; s++) acc[r][s] = 0.0f;

    for (int k0 = 0; k0 < N; k0 += 16) {
        #pragma unroll
        for (int r = 0; r < 16; r++) {
            int e = tid + r * 128;
            int cc = e >> 4, kk = e & 15;
            Vs[kk][cc] = V[(size_t)cc * N + k0 + kk];
        }
        #pragma unroll
        for (int r = 0; r < 8; r++) {
            int e = tid + r * 128;
            int kk = e >> 6, jj = e & 63;
            float2 ms = MS[k0 + kk];
            As2[kk][jj] = __expf(E[(size_t)(k0 + kk) * N + j0 + jj] - ms.x) * ms.y;
        }
        __syncthreads();

        #pragma unroll
        for (int kk = 0; kk < 16; kk++) {
            float4 a0 = *(const float4*)&Vs[kk][ty * 4];
            float4 a1 = *(const float4*)&Vs[kk][ty * 4 + 64];
            float4 b0 = *(const float4*)&As2[kk][tx * 4];
            float4 b1 = *(const float4*)&As2[kk][tx * 4 + 32];
            float a[8] = {a0.x, a0.y, a0.z, a0.w, a1.x, a1.y, a1.z, a1.w};
            float bb[8] = {b0.x, b0.y, b0.z, b0.w, b1.x, b1.y, b1.z, b1.w};
            #pragma unroll
            for (int r = 0; r < 8; r++)
                #pragma unroll
                for (int s = 0; s < 8; s++)
                    acc[r][s] += a[r] * bb[s];
        }
        __syncthreads();
    }

    const float gamma = *gamma_p;
    #pragma unroll
    for (int rh = 0; rh < 2; rh++)
        #pragma unroll
        for (int rr = 0; rr < 4; rr++) {
            int c = ty * 4 + rh * 64 + rr;
            #pragma unroll
            for (int sh = 0; sh < 2; sh++) {
                int j = j0 + tx * 4 + sh * 32;
                size_t idx = (size_t)b * C * N + (size_t)c * N + j;
                float4 o;
                o.x = fmaxf(acc[rh * 4 + rr][sh * 4 + 0], 0.0f);
                o.y = fmaxf(acc[rh * 4 + rr][sh * 4 + 1], 0.0f);
                o.z = fmaxf(acc[rh * 4 + rr][sh * 4 + 2], 0.0f);
                o.w = fmaxf(acc[rh * 4 + rr][sh * 4 + 3], 0.0f);
                *(float4*)&o_out[idx] = o;
                float4 xi = *(const float4*)&x[idx];
                float4 y;
                y.x = gamma * o.x + xi.x;
                y.y = gamma * o.y + xi.y;
                y.z = gamma * o.z + xi.z;
                y.w = gamma * o.w + xi.w;
                *(float4*)&y_out[idx] = y;
            }
        }
}

// ---------------------------------------------------------------------------
extern "C" void kernel_launch(void* const* d_in, const int* in_sizes, int n_in,
                              void* d_out, int out_size) {
    const float* x     = (const float*)d_in[0];
    const float* gamma = (const float*)d_in[1];
    float* out = (float*)d_out;

    float* y_sec = out;            // y
    float* o_sec = out + XE;       // out (post-relu)
    float* x_sec = out + 2 * XE;   // x passthrough
    float* g_sec = out + 3 * XE;   // gamma passthrough

    k1_gram<<<dim3(25, 25, B), 256>>>(x);
    k2_rowstats<<<dim3(N, B), 256>>>();
    k3_out<<<dim3(49, B), 128>>>(x, gamma, y_sec, o_sec);

    cudaMemcpyAsync(x_sec, x, XE * sizeof(float), cudaMemcpyDeviceToDevice);
    cudaMemcpyAsync(g_sec, gamma, sizeof(float), cudaMemcpyDeviceToDevice);
}

// round 3
// speedup vs baseline: 1.1587x; 1.1587x over previous
#include <cuda_runtime.h>

static constexpr int B = 8;
static constexpr int C = 128;
static constexpr int N = 3136;                  // 56*56
static constexpr size_t NN = (size_t)N * N;
static constexpr size_t XE = (size_t)B * C * N;

__device__ float  g_E[(size_t)B * NN];          // raw (pre-softmax) energies
__device__ float2 g_MS[(size_t)B * N];          // per-row (max, 1/sum)

typedef unsigned long long u64;

__device__ __forceinline__ u64 pack2(float lo, float hi) {
    u64 r;
    asm("mov.b64 %0, {%1, %2};" : "=l"(r) : "f"(lo), "f"(hi));
    return r;
}
__device__ __forceinline__ float2 unpack2(u64 v) {
    float2 f;
    asm("mov.b64 {%0, %1}, %2;" : "=f"(f.x), "=f"(f.y) : "l"(v));
    return f;
}
__device__ __forceinline__ void fma2(u64& d, u64 a, u64 b) {
    asm("fma.rn.f32x2 %0, %1, %2, %0;" : "+l"(d) : "l"(a), "l"(b));
}

// ---------------------------------------------------------------------------
// K1: E = V^T V, diag zeroed. 128x128 tile, 8x8 microtile via fma.rn.f32x2,
// symmetry (tj>=ti), mirror via smem transpose slabs. grid(25,25,B), 256 thr.
// ---------------------------------------------------------------------------
__global__ __launch_bounds__(256, 2) void k1_gram(const float* __restrict__ x) {
    const int ti = blockIdx.x, tj = blockIdx.y, b = blockIdx.z;
    if (tj < ti) return;

    __shared__ float As[8][128];
    __shared__ float Bsh[8][128];
    __shared__ float T[32][129];

    const float* V = x + (size_t)b * C * N;
    const int tid = threadIdx.x;
    const int tx = tid & 15, ty = tid >> 4;
    const int i0 = ti * 128, j0 = tj * 128;

    u64 acc2[8][4];
    #pragma unroll
    for (int r = 0; r < 8; r++)
        #pragma unroll
        for (int s = 0; s < 4; s++) acc2[r][s] = 0ULL;

    for (int c0 = 0; c0 < C; c0 += 8) {
        #pragma unroll
        for (int r = 0; r < 4; r++) {
            int e = tid + r * 256;
            int cc = e >> 7, col = e & 127;
            const float* row = V + (size_t)(c0 + cc) * N;
            As[cc][col]  = row[min(i0 + col, N - 1)];
            Bsh[cc][col] = row[min(j0 + col, N - 1)];
        }
        __syncthreads();

        #pragma unroll
        for (int cc = 0; cc < 8; cc++) {
            float4 a0 = *(const float4*)&As[cc][ty * 4];
            float4 a1 = *(const float4*)&As[cc][ty * 4 + 64];
            ulonglong2 b0 = *(const ulonglong2*)&Bsh[cc][tx * 4];
            ulonglong2 b1 = *(const ulonglong2*)&Bsh[cc][tx * 4 + 64];
            u64 bb[4] = {b0.x, b0.y, b1.x, b1.y};
            float a[8] = {a0.x, a0.y, a0.z, a0.w, a1.x, a1.y, a1.z, a1.w};
            u64 ap[8];
            #pragma unroll
            for (int r = 0; r < 8; r++) ap[r] = pack2(a[r], a[r]);
            #pragma unroll
            for (int r = 0; r < 8; r++)
                #pragma unroll
                for (int s = 0; s < 4; s++)
                    fma2(acc2[r][s], ap[r], bb[s]);
        }
        __syncthreads();
    }

    // Unpack accumulators: acc[r][sh*4 + k] with sh from pair index
    float accf[8][8];
    #pragma unroll
    for (int r = 0; r < 8; r++)
        #pragma unroll
        for (int s = 0; s < 4; s++) {
            float2 f = unpack2(acc2[r][s]);
            accf[r][s * 2 + 0] = f.x;
            accf[r][s * 2 + 1] = f.y;
        }
    // layout: s=0,1 -> j=tx*4+0..3 ; s=2,3 -> j=tx*4+64..67

    float* E = g_E + (size_t)b * NN;

    #pragma unroll
    for (int rh = 0; rh < 2; rh++)
        #pragma unroll
        for (int rr = 0; rr < 4; rr++) {
            int i = i0 + ty * 4 + rh * 64 + rr;
            if (i >= N) continue;
            #pragma unroll
            for (int sh = 0; sh < 2; sh++) {
                int j = j0 + tx * 4 + sh * 64;
                if (j >= N) continue;
                float4 v;
                v.x = accf[rh * 4 + rr][sh * 4 + 0];
                v.y = accf[rh * 4 + rr][sh * 4 + 1];
                v.z = accf[rh * 4 + rr][sh * 4 + 2];
                v.w = accf[rh * 4 + rr][sh * 4 + 3];
                if (ti == tj) {
                    int d = i - j;
                    if (d >= 0 && d < 4) ((float*)&v)[d] = 0.0f;
                }
                *(float4*)&E[(size_t)i * N + j] = v;
            }
        }

    if (ti != tj) {
        #pragma unroll
        for (int p = 0; p < 4; p++) {
            __syncthreads();
            int sh = p >> 1;
            int want_hi = p & 1;
            if ((tx >> 3) == want_hi) {
                int txl = tx & 7;
                #pragma unroll
                for (int s = 0; s < 4; s++) {
                    int lc = txl * 4 + s;
                    #pragma unroll
                    for (int rh = 0; rh < 2; rh++)
                        #pragma unroll
                        for (int rr = 0; rr < 4; rr++)
                            T[lc][ty * 4 + rh * 64 + rr] = accf[rh * 4 + rr][sh * 4 + s];
                }
            }
            __syncthreads();
            #pragma unroll
            for (int q = 0; q < 16; q++) {
                int e = tid + q * 256;
                int lr = e >> 7, lcx = e & 127;
                int jr = j0 + p * 32 + lr;
                int ic = i0 + lcx;
                if (jr < N && ic < N)
                    E[(size_t)jr * N + ic] = T[lr][lcx];
            }
        }
    }
}

// ---------------------------------------------------------------------------
// K2: per-row (max, 1/sum(exp)) only. grid (N, B), 256 thr.
// ---------------------------------------------------------------------------
__global__ __launch_bounds__(256) void k2_rowstats() {
    const int row = blockIdx.x, b = blockIdx.y;
    const float* E = g_E + (size_t)b * NN + (size_t)row * N;

    __shared__ float sv[N];
    __shared__ float red[256];
    const int tid = threadIdx.x;

    float m = -1e30f;
    for (int j = tid; j < N; j += 256) {
        float v = E[j];
        sv[j] = v;
        m = fmaxf(m, v);
    }
    red[tid] = m;
    __syncthreads();
    #pragma unroll
    for (int s = 128; s > 0; s >>= 1) {
        if (tid < s) red[tid] = fmaxf(red[tid], red[tid + s]);
        __syncthreads();
    }
    m = red[0];
    __syncthreads();

    float sum = 0.0f;
    for (int j = tid; j < N; j += 256)
        sum += __expf(sv[j] - m);
    red[tid] = sum;
    __syncthreads();
    #pragma unroll
    for (int s = 128; s > 0; s >>= 1) {
        if (tid < s) red[tid] += red[tid + s];
        __syncthreads();
    }
    if (tid == 0) g_MS[(size_t)b * N + row] = make_float2(m, 1.0f / red[0]);
}

// ---------------------------------------------------------------------------
// K3: out[c,j] = sum_i V[c,i] * softmax(E)[i,j], softmax applied on the fly,
// fma.rn.f32x2 inner loop. 128(c)x64(j) tile, 8x8 micro, 128 thr. grid(49,B).
// Fused relu + y = gamma*out + x epilogue.
// ---------------------------------------------------------------------------
__global__ __launch_bounds__(128, 4) void k3_out(const float* __restrict__ x,
                                                 const float* __restrict__ gamma_p,
                                                 float* __restrict__ y_out,
                                                 float* __restrict__ o_out) {
    const int b = blockIdx.y;
    const int j0 = blockIdx.x * 64;
    const float* V = x + (size_t)b * C * N;
    const float* E = g_E + (size_t)b * NN;
    const float2* MS = g_MS + (size_t)b * N;

    __shared__ float Vs[16][132];   // [kk][c], padded (132*4 % 16 == 0)
    __shared__ float As2[16][64];   // [kk][jj]

    const int tid = threadIdx.x;
    const int tx = tid & 7, ty = tid >> 3;

    u64 acc2[8][4];
    #pragma unroll
    for (int r = 0; r < 8; r++)
        #pragma unroll
        for (int s = 0; s < 4; s++) acc2[r][s] = 0ULL;

    for (int k0 = 0; k0 < N; k0 += 16) {
        #pragma unroll
        for (int r = 0; r < 16; r++) {
            int e = tid + r * 128;
            int cc = e >> 4, kk = e & 15;
            Vs[kk][cc] = V[(size_t)cc * N + k0 + kk];
        }
        #pragma unroll
        for (int r = 0; r < 8; r++) {
            int e = tid + r * 128;
            int kk = e >> 6, jj = e & 63;
            float2 ms = MS[k0 + kk];
            As2[kk][jj] = __expf(E[(size_t)(k0 + kk) * N + j0 + jj] - ms.x) * ms.y;
        }
        __syncthreads();

        #pragma unroll
        for (int kk = 0; kk < 16; kk++) {
            float4 a0 = *(const float4*)&Vs[kk][ty * 4];
            float4 a1 = *(const float4*)&Vs[kk][ty * 4 + 64];
            ulonglong2 b0 = *(const ulonglong2*)&As2[kk][tx * 4];
            ulonglong2 b1 = *(const ulonglong2*)&As2[kk][tx * 4 + 32];
            u64 bb[4] = {b0.x, b0.y, b1.x, b1.y};
            float a[8] = {a0.x, a0.y, a0.z, a0.w, a1.x, a1.y, a1.z, a1.w};
            u64 ap[8];
            #pragma unroll
            for (int r = 0; r < 8; r++) ap[r] = pack2(a[r], a[r]);
            #pragma unroll
            for (int r = 0; r < 8; r++)
                #pragma unroll
                for (int s = 0; s < 4; s++)
                    fma2(acc2[r][s], ap[r], bb[s]);
        }
        __syncthreads();
    }

    float accf[8][8];
    #pragma unroll
    for (int r = 0; r < 8; r++)
        #pragma unroll
        for (int s = 0; s < 4; s++) {
            float2 f = unpack2(acc2[r][s]);
            accf[r][s * 2 + 0] = f.x;
            accf[r][s * 2 + 1] = f.y;
        }
    // s=0,1 -> j=tx*4+0..3 ; s=2,3 -> j=tx*4+32..35

    const float gamma = *gamma_p;
    #pragma unroll
    for (int rh = 0; rh < 2; rh++)
        #pragma unroll
        for (int rr = 0; rr < 4; rr++) {
            int c = ty * 4 + rh * 64 + rr;
            #pragma unroll
            for (int sh = 0; sh < 2; sh++) {
                int j = j0 + tx * 4 + sh * 32;
                size_t idx = (size_t)b * C * N + (size_t)c * N + j;
                float4 o;
                o.x = fmaxf(accf[rh * 4 + rr][sh * 4 + 0], 0.0f);
                o.y = fmaxf(accf[rh * 4 + rr][sh * 4 + 1], 0.0f);
                o.z = fmaxf(accf[rh * 4 + rr][sh * 4 + 2], 0.0f);
                o.w = fmaxf(accf[rh * 4 + rr][sh * 4 + 3], 0.0f);
                *(float4*)&o_out[idx] = o;
                float4 xi = *(const float4*)&x[idx];
                float4 y;
                y.x = gamma * o.x + xi.x;
                y.y = gamma * o.y + xi.y;
                y.z = gamma * o.z + xi.z;
                y.w = gamma * o.w + xi.w;
                *(float4*)&y_out[idx] = y;
            }
        }
}

// ---------------------------------------------------------------------------
extern "C" void kernel_launch(void* const* d_in, const int* in_sizes, int n_in,
                              void* d_out, int out_size) {
    const float* x     = (const float*)d_in[0];
    const float* gamma = (const float*)d_in[1];
    float* out = (float*)d_out;

    float* y_sec = out;            // y
    float* o_sec = out + XE;       // out (post-relu)
    float* x_sec = out + 2 * XE;   // x passthrough
    float* g_sec = out + 3 * XE;   // gamma passthrough

    k1_gram<<<dim3(25, 25, B), 256>>>(x);
    k2_rowstats<<<dim3(N, B), 256>>>();
    k3_out<<<dim3(49, B), 128>>>(x, gamma, y_sec, o_sec);

    cudaMemcpyAsync(x_sec, x, XE * sizeof(float), cudaMemcpyDeviceToDevice);
    cudaMemcpyAsync(g_sec, gamma, sizeof(float), cudaMemcpyDeviceToDevice);
}

// round 5
// speedup vs baseline: 1.9157x; 1.6534x over previous
#include <cuda_runtime.h>
#include <cuda_bf16.h>
#include <cstdint>

static constexpr int B_ = 8;
static constexpr int C_ = 128;
static constexpr int N_ = 3136;                 // 56*56
static constexpr int NT = 25;                   // ceil(N/128)
static constexpr size_t NN = (size_t)N_ * N_;
static constexpr size_t XE = (size_t)B_ * C_ * N_;

__device__ float         g_E[(size_t)B_ * NN];           // masked energies (fp32)
__device__ __nv_bfloat16 g_xT_hi[(size_t)B_ * N_ * C_];  // x^T split hi  [b][n][c]
__device__ __nv_bfloat16 g_xT_lo[(size_t)B_ * N_ * C_];  // x^T split lo
__device__ float2        g_part[(size_t)B_ * NT * N_];   // per (b, coltile, i): (max, sumexp)
__device__ float2        g_MS[(size_t)B_ * N_];          // per (b, i): (max, 1/sum)

// ---------------------------------------------------------------------------
// helpers
// ---------------------------------------------------------------------------
__device__ __forceinline__ uint32_t smem_u32(const void* p) {
    uint32_t a;
    asm("{ .reg .u64 t; cvta.to.shared.u64 t, %1; cvt.u32.u64 %0, t; }" : "=r"(a) : "l"(p));
    return a;
}
__device__ __forceinline__ void ldm_x4(uint32_t* r, uint32_t a) {
    asm volatile("ldmatrix.sync.aligned.m8n8.x4.shared.b16 {%0,%1,%2,%3}, [%4];"
                 : "=r"(r[0]), "=r"(r[1]), "=r"(r[2]), "=r"(r[3]) : "r"(a));
}
__device__ __forceinline__ void ldm_x2(uint32_t* r, uint32_t a) {
    asm volatile("ldmatrix.sync.aligned.m8n8.x2.shared.b16 {%0,%1}, [%2];"
                 : "=r"(r[0]), "=r"(r[1]) : "r"(a));
}
__device__ __forceinline__ void mma_bf16(float* d, const uint32_t* a, const uint32_t* b) {
    asm volatile("mma.sync.aligned.m16n8k16.row.col.f32.bf16.bf16.f32 "
                 "{%0,%1,%2,%3}, {%4,%5,%6,%7}, {%8,%9}, {%0,%1,%2,%3};"
                 : "+f"(d[0]), "+f"(d[1]), "+f"(d[2]), "+f"(d[3])
                 : "r"(a[0]), "r"(a[1]), "r"(a[2]), "r"(a[3]), "r"(b[0]), "r"(b[1]));
}

// smem operand tiles: 128 rows x 32 bf16 (k-chunk), pitch 40 bf16 = 80B
static constexpr int PITCHB = 80;
static constexpr int TILE_BYTES = 128 * PITCHB;              // 10240
static constexpr int SA_H = 0, SA_L = 10240, SB_H = 20480, SB_L = 30720;
static constexpr int STG = 40960;                            // fp32 stage 128x133
static constexpr int K1_SMEM = STG + 128 * 133 * 4;          // 109056
static constexpr int K3_SMEM = 40960;

// ---------------------------------------------------------------------------
// K0: split/transpose x -> xT_hi/lo [b][n][c]
// ---------------------------------------------------------------------------
__global__ void k0_split(const float* __restrict__ x) {
    __shared__ float t[32][33];
    const int b = blockIdx.z, c0 = blockIdx.x * 32, n0 = blockIdx.y * 32;
    const int tx = threadIdx.x, ty = threadIdx.y;   // 32 x 8
    const float* xb = x + (size_t)b * C_ * N_;
    #pragma unroll
    for (int r = 0; r < 4; r++) {
        int c = ty + r * 8;
        t[c][tx] = xb[(size_t)(c0 + c) * N_ + n0 + tx];
    }
    __syncthreads();
    __nv_bfloat16* Th = g_xT_hi + (size_t)b * N_ * C_;
    __nv_bfloat16* Tl = g_xT_lo + (size_t)b * N_ * C_;
    #pragma unroll
    for (int r = 0; r < 4; r++) {
        int n = ty + r * 8;
        float v = t[tx][n];
        __nv_bfloat16 h = __float2bfloat16(v);
        __nv_bfloat16 l = __float2bfloat16(v - __bfloat162float(h));
        size_t o = (size_t)(n0 + n) * C_ + c0 + tx;
        Th[o] = h; Tl[o] = l;
    }
}

// ---------------------------------------------------------------------------
// K1: E-tile = xT * xT^T (128x128, K=C=128, 3 split passes) via mma.sync.
// Symmetry tj>=ti; mirror + mirrored softmax partials via fp32 stage.
// grid (25, 25, B), 256 threads (8 warps as 2m x 4n, warp tile 64x32).
// ---------------------------------------------------------------------------
__global__ void __launch_bounds__(256) k1_gram() {
    extern __shared__ char smem[];
    const uint32_t sb = smem_u32(smem);
    const int tid = threadIdx.x, wid = tid >> 5, lane = tid & 31;
    const int g = lane >> 2, t4 = lane & 3;
    const int ti = blockIdx.x, tj = blockIdx.y, b = blockIdx.z;
    if (tj < ti) return;
    const int i0 = ti * 128, j0 = tj * 128;
    const int wm = wid & 1, wn = wid >> 1;

    // ldmatrix lane address components
    const int ab = lane >> 3;
    const int a_row = (ab & 1) * 8 + (lane & 7);
    const int a_colb = ((ab >> 1) * 8) * 2;       // byte offset within k-chunk
    const int b_row = lane & 7;
    const int b_colb = (((lane >> 3) & 1) * 8) * 2;

    const __nv_bfloat16* Xh = g_xT_hi + (size_t)b * N_ * C_;
    const __nv_bfloat16* Xl = g_xT_lo + (size_t)b * N_ * C_;

    float acc[4][4][4];
    #pragma unroll
    for (int i = 0; i < 4; i++)
        #pragma unroll
        for (int j = 0; j < 4; j++)
            #pragma unroll
            for (int q = 0; q < 4; q++) acc[i][j][q] = 0.0f;

    for (int c0 = 0; c0 < C_; c0 += 32) {
        for (int e = tid; e < 2048; e += 256) {
            int row = e >> 4, cp = e & 15;
            int gra = min(i0 + row, N_ - 1);
            int grb = min(j0 + row, N_ - 1);
            const uint32_t* pah = (const uint32_t*)(Xh + (size_t)gra * C_ + c0);
            const uint32_t* pal = (const uint32_t*)(Xl + (size_t)gra * C_ + c0);
            const uint32_t* pbh = (const uint32_t*)(Xh + (size_t)grb * C_ + c0);
            const uint32_t* pbl = (const uint32_t*)(Xl + (size_t)grb * C_ + c0);
            int o = row * PITCHB + cp * 4;
            *(uint32_t*)(smem + SA_H + o) = pah[cp];
            *(uint32_t*)(smem + SA_L + o) = pal[cp];
            *(uint32_t*)(smem + SB_H + o) = pbh[cp];
            *(uint32_t*)(smem + SB_L + o) = pbl[cp];
        }
        __syncthreads();

        #pragma unroll
        for (int ks = 0; ks < 2; ks++) {
            const int kb = ks * 32;
            uint32_t af[4][4], bfr[4][2];
            // pass 1: (Ah, Bh)
            #pragma unroll
            for (int ma = 0; ma < 4; ma++)
                ldm_x4(af[ma], sb + SA_H + (wm * 64 + ma * 16 + a_row) * PITCHB + kb + a_colb);
            #pragma unroll
            for (int na = 0; na < 4; na++)
                ldm_x2(bfr[na], sb + SB_H + (wn * 32 + na * 8 + b_row) * PITCHB + kb + b_colb);
            #pragma unroll
            for (int ma = 0; ma < 4; ma++)
                #pragma unroll
                for (int na = 0; na < 4; na++) mma_bf16(acc[ma][na], af[ma], bfr[na]);
            // pass 2: (Al, Bh)
            #pragma unroll
            for (int ma = 0; ma < 4; ma++)
                ldm_x4(af[ma], sb + SA_L + (wm * 64 + ma * 16 + a_row) * PITCHB + kb + a_colb);
            #pragma unroll
            for (int ma = 0; ma < 4; ma++)
                #pragma unroll
                for (int na = 0; na < 4; na++) mma_bf16(acc[ma][na], af[ma], bfr[na]);
            // pass 3: (Ah, Bl)
            #pragma unroll
            for (int ma = 0; ma < 4; ma++)
                ldm_x4(af[ma], sb + SA_H + (wm * 64 + ma * 16 + a_row) * PITCHB + kb + a_colb);
            #pragma unroll
            for (int na = 0; na < 4; na++)
                ldm_x2(bfr[na], sb + SB_L + (wn * 32 + na * 8 + b_row) * PITCHB + kb + b_colb);
            #pragma unroll
            for (int ma = 0; ma < 4; ma++)
                #pragma unroll
                for (int na = 0; na < 4; na++) mma_bf16(acc[ma][na], af[ma], bfr[na]);
        }
        __syncthreads();
    }

    // stage fp32 tile (pitch 133) with diagonal mask
    float* stg = (float*)(smem + STG);
    const bool diagblk = (ti == tj);
    #pragma unroll
    for (int ma = 0; ma < 4; ma++)
        #pragma unroll
        for (int na = 0; na < 4; na++) {
            int r0 = wm * 64 + ma * 16 + g;
            int cc = wn * 32 + na * 8 + t4 * 2;
            float d0 = acc[ma][na][0], d1 = acc[ma][na][1];
            float d2 = acc[ma][na][2], d3 = acc[ma][na][3];
            if (diagblk) {
                if (r0 == cc) d0 = 0.0f;
                if (r0 == cc + 1) d1 = 0.0f;
                if (r0 + 8 == cc) d2 = 0.0f;
                if (r0 + 8 == cc + 1) d3 = 0.0f;
            }
            stg[r0 * 133 + cc] = d0;
            stg[r0 * 133 + cc + 1] = d1;
            stg[(r0 + 8) * 133 + cc] = d2;
            stg[(r0 + 8) * 133 + cc + 1] = d3;
        }
    __syncthreads();

    const int ilim = min(128, N_ - i0), jlim = min(128, N_ - j0);

    if (tid < 128) {                      // main partials: rows of tile ti over cols tile tj
        int row = tid;
        if (row < ilim) {
            float m = -1e30f;
            for (int c = 0; c < jlim; c++) m = fmaxf(m, stg[row * 133 + c]);
            float s = 0.0f;
            for (int c = 0; c < jlim; c++) s += __expf(stg[row * 133 + c] - m);
            g_part[((size_t)b * NT + tj) * N_ + i0 + row] = make_float2(m, s);
        }
    } else if (ti != tj) {                // mirrored partials: rows of tile tj over cols tile ti
        int jr = tid - 128;
        if (jr < jlim) {
            float m = -1e30f;
            for (int ic = 0; ic < ilim; ic++) m = fmaxf(m, stg[ic * 133 + jr]);
            float s = 0.0f;
            for (int ic = 0; ic < ilim; ic++) s += __expf(stg[ic * 133 + jr] - m);
            g_part[((size_t)b * NT + ti) * N_ + j0 + jr] = make_float2(m, s);
        }
    }

    float* E = g_E + (size_t)b * NN;
    for (int e = tid; e < 16384; e += 256) {
        int r = e >> 7, c = e & 127;
        if (r < ilim && c < jlim) E[(size_t)(i0 + r) * N_ + j0 + c] = stg[r * 133 + c];
    }
    if (ti != tj) {
        for (int e = tid; e < 16384; e += 256) {
            int jr = e >> 7, ic = e & 127;
            if (jr < jlim && ic < ilim) E[(size_t)(j0 + jr) * N_ + i0 + ic] = stg[ic * 133 + jr];
        }
    }
}

// ---------------------------------------------------------------------------
// K2: reduce 25 partials per row -> (max, 1/sum)
// ---------------------------------------------------------------------------
__global__ void k2_reduce() {
    int gidx = blockIdx.x * 256 + threadIdx.x;
    if (gidx >= B_ * N_) return;
    int b = gidx / N_, i = gidx - b * N_;
    const float2* p = g_part + (size_t)b * NT * N_ + i;
    float m = -1e30f;
    #pragma unroll
    for (int t = 0; t < NT; t++) m = fmaxf(m, p[(size_t)t * N_].x);
    float s = 0.0f;
    #pragma unroll
    for (int t = 0; t < NT; t++) {
        float2 v = p[(size_t)t * N_];
        s += v.y * __expf(v.x - m);
    }
    g_MS[gidx] = make_float2(m, 1.0f / s);
}

// ---------------------------------------------------------------------------
// K3: out[c,j] = sum_i V[c,i] * att[i,j], att[i][j] = exp(E[j][i]-m_i)*inv_i
// (E symmetric). M=c=128, N=j=128, K=i over 98 chunks of 32. 3 split passes.
// grid (25, B), 256 threads. Fused relu/gamma/residual epilogue.
// ---------------------------------------------------------------------------
__global__ void __launch_bounds__(256) k3_out(const float* __restrict__ x,
                                              const float* __restrict__ gamma_p,
                                              float* __restrict__ y_out,
                                              float* __restrict__ o_out) {
    extern __shared__ char smem[];
    const uint32_t sb = smem_u32(smem);
    const int tid = threadIdx.x, wid = tid >> 5, lane = tid & 31;
    const int g = lane >> 2, t4 = lane & 3;
    const int b = blockIdx.y, j0 = blockIdx.x * 128;
    const int wm = wid & 1, wn = wid >> 1;

    const int ab = lane >> 3;
    const int a_row = (ab & 1) * 8 + (lane & 7);
    const int a_colb = ((ab >> 1) * 8) * 2;
    const int b_row = lane & 7;
    const int b_colb = (((lane >> 3) & 1) * 8) * 2;

    const float* xb = x + (size_t)b * C_ * N_;
    const float* E = g_E + (size_t)b * NN;
    const float2* MS = g_MS + (size_t)b * N_;

    float acc[4][4][4];
    #pragma unroll
    for (int i = 0; i < 4; i++)
        #pragma unroll
        for (int j = 0; j < 4; j++)
            #pragma unroll
            for (int q = 0; q < 4; q++) acc[i][j][q] = 0.0f;

    for (int kc = 0; kc < 98; kc++) {
        const int iC = kc * 32;
        // V tile: rows c, cols i (split on the fly from fp32 x)
        for (int e = tid; e < 2048; e += 256) {
            int c = e >> 4, p = e & 15;
            float2 f = *(const float2*)(xb + (size_t)c * N_ + iC + 2 * p);
            __nv_bfloat16 h0 = __float2bfloat16(f.x);
            __nv_bfloat16 h1 = __float2bfloat16(f.y);
            __nv_bfloat16 l0 = __float2bfloat16(f.x - __bfloat162float(h0));
            __nv_bfloat16 l1 = __float2bfloat16(f.y - __bfloat162float(h1));
            int o = c * PITCHB + p * 4;
            *(__nv_bfloat162*)(smem + SA_H + o) = __halves2bfloat162(h0, h1);
            *(__nv_bfloat162*)(smem + SA_L + o) = __halves2bfloat162(l0, l1);
        }
        // att tile: rows j, cols i via symmetric E + per-i column stats
        for (int e = tid; e < 2048; e += 256) {
            int jl = e >> 4, p = e & 15;
            int jr = min(j0 + jl, N_ - 1);
            float2 f = *(const float2*)(E + (size_t)jr * N_ + iC + 2 * p);
            float2 m0 = MS[iC + 2 * p];
            float2 m1 = MS[iC + 2 * p + 1];
            float a0 = __expf(f.x - m0.x) * m0.y;
            float a1 = __expf(f.y - m1.x) * m1.y;
            __nv_bfloat16 h0 = __float2bfloat16(a0);
            __nv_bfloat16 h1 = __float2bfloat16(a1);
            __nv_bfloat16 l0 = __float2bfloat16(a0 - __bfloat162float(h0));
            __nv_bfloat16 l1 = __float2bfloat16(a1 - __bfloat162float(h1));
            int o = jl * PITCHB + p * 4;
            *(__nv_bfloat162*)(smem + SB_H + o) = __halves2bfloat162(h0, h1);
            *(__nv_bfloat162*)(smem + SB_L + o) = __halves2bfloat162(l0, l1);
        }
        __syncthreads();

        #pragma unroll
        for (int ks = 0; ks < 2; ks++) {
            const int kb = ks * 32;
            uint32_t af[4][4], bfr[4][2];
            #pragma unroll
            for (int ma = 0; ma < 4; ma++)
                ldm_x4(af[ma], sb + SA_H + (wm * 64 + ma * 16 + a_row) * PITCHB + kb + a_colb);
            #pragma unroll
            for (int na = 0; na < 4; na++)
                ldm_x2(bfr[na], sb + SB_H + (wn * 32 + na * 8 + b_row) * PITCHB + kb + b_colb);
            #pragma unroll
            for (int ma = 0; ma < 4; ma++)
                #pragma unroll
                for (int na = 0; na < 4; na++) mma_bf16(acc[ma][na], af[ma], bfr[na]);
            #pragma unroll
            for (int ma = 0; ma < 4; ma++)
                ldm_x4(af[ma], sb + SA_L + (wm * 64 + ma * 16 + a_row) * PITCHB + kb + a_colb);
            #pragma unroll
            for (int ma = 0; ma < 4; ma++)
                #pragma unroll
                for (int na = 0; na < 4; na++) mma_bf16(acc[ma][na], af[ma], bfr[na]);
            #pragma unroll
            for (int ma = 0; ma < 4; ma++)
                ldm_x4(af[ma], sb + SA_H + (wm * 64 + ma * 16 + a_row) * PITCHB + kb + a_colb);
            #pragma unroll
            for (int na = 0; na < 4; na++)
                ldm_x2(bfr[na], sb + SB_L + (wn * 32 + na * 8 + b_row) * PITCHB + kb + b_colb);
            #pragma unroll
            for (int ma = 0; ma < 4; ma++)
                #pragma unroll
                for (int na = 0; na < 4; na++) mma_bf16(acc[ma][na], af[ma], bfr[na]);
        }
        __syncthreads();
    }

    // epilogue: direct stores (32B sector per lane quad)
    const float gamma = *gamma_p;
    #pragma unroll
    for (int ma = 0; ma < 4; ma++)
        #pragma unroll
        for (int na = 0; na < 4; na++) {
            int c = wm * 64 + ma * 16 + g;
            int j = j0 + wn * 32 + na * 8 + t4 * 2;
            if (j < N_) {
                size_t idx0 = ((size_t)b * C_ + c) * N_ + j;
                size_t idx1 = ((size_t)b * C_ + c + 8) * N_ + j;
                float o0 = fmaxf(acc[ma][na][0], 0.0f);
                float o1 = fmaxf(acc[ma][na][1], 0.0f);
                float o2 = fmaxf(acc[ma][na][2], 0.0f);
                float o3 = fmaxf(acc[ma][na][3], 0.0f);
                float2 xi0 = *(const float2*)&xb[(size_t)c * N_ + j];
                float2 xi1 = *(const float2*)&xb[(size_t)(c + 8) * N_ + j];
                *(float2*)&o_out[idx0] = make_float2(o0, o1);
                *(float2*)&o_out[idx1] = make_float2(o2, o3);
                *(float2*)&y_out[idx0] = make_float2(gamma * o0 + xi0.x, gamma * o1 + xi0.y);
                *(float2*)&y_out[idx1] = make_float2(gamma * o2 + xi1.x, gamma * o3 + xi1.y);
            }
        }
}

// ---------------------------------------------------------------------------
extern "C" void kernel_launch(void* const* d_in, const int* in_sizes, int n_in,
                              void* d_out, int out_size) {
    const float* x     = (const float*)d_in[0];
    const float* gamma = (const float*)d_in[1];
    float* out = (float*)d_out;

    float* y_sec = out;
    float* o_sec = out + XE;
    float* x_sec = out + 2 * XE;
    float* g_sec = out + 3 * XE;

    cudaFuncSetAttribute(k1_gram, cudaFuncAttributeMaxDynamicSharedMemorySize, K1_SMEM);
    cudaFuncSetAttribute(k3_out, cudaFuncAttributeMaxDynamicSharedMemorySize, K3_SMEM);

    k0_split<<<dim3(4, 98, B_), dim3(32, 8)>>>(x);
    k1_gram<<<dim3(NT, NT, B_), 256, K1_SMEM>>>();
    k2_reduce<<<(B_ * N_ + 255) / 256, 256>>>();
    k3_out<<<dim3(NT, B_), 256, K3_SMEM>>>(x, gamma, y_sec, o_sec);

    cudaMemcpyAsync(x_sec, x, XE * sizeof(float), cudaMemcpyDeviceToDevice);
    cudaMemcpyAsync(g_sec, gamma, sizeof(float), cudaMemcpyDeviceToDevice);
}

// round 6
// speedup vs baseline: 2.4008x; 1.2532x over previous
#include <cuda_runtime.h>
#include <cuda_bf16.h>
#include <cstdint>

static constexpr int B_ = 8;
static constexpr int C_ = 128;
static constexpr int N_ = 3136;                 // 56*56
static constexpr int NT = 25;                   // ceil(N/128)
static constexpr size_t NN = (size_t)N_ * N_;
static constexpr size_t XE = (size_t)B_ * C_ * N_;

__device__ __nv_bfloat16 g_P_hi[(size_t)B_ * NN];        // exp(E) split hi
__device__ __nv_bfloat16 g_P_lo[(size_t)B_ * NN];        // exp(E) split lo
__device__ __nv_bfloat16 g_xT_hi[(size_t)B_ * N_ * C_];  // x^T split hi  [b][n][c]
__device__ __nv_bfloat16 g_xT_lo[(size_t)B_ * N_ * C_];  // x^T split lo
__device__ __nv_bfloat16 g_V_hi[XE];                     // (x * inv) split hi [b][c][i]
__device__ __nv_bfloat16 g_V_lo[XE];
__device__ float         g_psum[(size_t)B_ * NT * N_];   // partial row sums of P
__device__ float         g_inv[(size_t)B_ * N_];         // 1 / rowsum

// ---------------------------------------------------------------------------
// helpers
// ---------------------------------------------------------------------------
__device__ __forceinline__ uint32_t smem_u32(const void* p) {
    uint32_t a;
    asm("{ .reg .u64 t; cvta.to.shared.u64 t, %1; cvt.u32.u64 %0, t; }" : "=r"(a) : "l"(p));
    return a;
}
__device__ __forceinline__ void ldm_x4(uint32_t* r, uint32_t a) {
    asm volatile("ldmatrix.sync.aligned.m8n8.x4.shared.b16 {%0,%1,%2,%3}, [%4];"
                 : "=r"(r[0]), "=r"(r[1]), "=r"(r[2]), "=r"(r[3]) : "r"(a));
}
__device__ __forceinline__ void ldm_x2(uint32_t* r, uint32_t a) {
    asm volatile("ldmatrix.sync.aligned.m8n8.x2.shared.b16 {%0,%1}, [%2];"
                 : "=r"(r[0]), "=r"(r[1]) : "r"(a));
}
__device__ __forceinline__ void mma_bf16(float* d, const uint32_t* a, const uint32_t* b) {
    asm volatile("mma.sync.aligned.m16n8k16.row.col.f32.bf16.bf16.f32 "
                 "{%0,%1,%2,%3}, {%4,%5,%6,%7}, {%8,%9}, {%0,%1,%2,%3};"
                 : "+f"(d[0]), "+f"(d[1]), "+f"(d[2]), "+f"(d[3])
                 : "r"(a[0]), "r"(a[1]), "r"(a[2]), "r"(a[3]), "r"(b[0]), "r"(b[1]));
}
__device__ __forceinline__ void split_bf16(float v, __nv_bfloat16& h, __nv_bfloat16& l) {
    h = __float2bfloat16(v);
    l = __float2bfloat16(v - __bfloat162float(h));
}

static constexpr int PITCHB = 80;               // 32 bf16 k-chunk rows, pitch 40 bf16
static constexpr int TILEB = 128 * PITCHB;      // 10240
static constexpr int SA_H = 0, SA_L = 10240, SB_H = 20480, SB_L = 30720;
static constexpr int BUFB = 40960;
static constexpr int STG = 40960;               // k1 fp32 stage 128x133
static constexpr int K1_SMEM = STG + 128 * 133 * 4;   // 109056
static constexpr int K3_SMEM = 2 * BUFB;              // 81920

// ---------------------------------------------------------------------------
// K0: split/transpose x -> xT_hi/lo [b][n][c]
// ---------------------------------------------------------------------------
__global__ void k0_split(const float* __restrict__ x) {
    __shared__ float t[32][33];
    const int b = blockIdx.z, c0 = blockIdx.x * 32, n0 = blockIdx.y * 32;
    const int tx = threadIdx.x, ty = threadIdx.y;   // 32 x 8
    const float* xb = x + (size_t)b * C_ * N_;
    #pragma unroll
    for (int r = 0; r < 4; r++) {
        int c = ty + r * 8;
        t[c][tx] = xb[(size_t)(c0 + c) * N_ + n0 + tx];
    }
    __syncthreads();
    __nv_bfloat16* Th = g_xT_hi + (size_t)b * N_ * C_;
    __nv_bfloat16* Tl = g_xT_lo + (size_t)b * N_ * C_;
    #pragma unroll
    for (int r = 0; r < 4; r++) {
        int n = ty + r * 8;
        float v = t[tx][n];
        __nv_bfloat16 h, l;
        split_bf16(v, h, l);
        size_t o = (size_t)(n0 + n) * C_ + c0 + tx;
        Th[o] = h; Tl[o] = l;
    }
}

// ---------------------------------------------------------------------------
// K1: P-tile = exp(mask(xT * xT^T)) via mma.sync (3 split passes), symmetry
// tj>=ti with mirror. Writes P hi/lo + partial row sums.
// grid (25, 25, B), 256 threads (8 warps 2m x 4n, warp tile 64x32).
// ---------------------------------------------------------------------------
__global__ void __launch_bounds__(256) k1_gram() {
    extern __shared__ char smem[];
    const uint32_t sb = smem_u32(smem);
    const int tid = threadIdx.x, wid = tid >> 5, lane = tid & 31;
    const int g = lane >> 2, t4 = lane & 3;
    const int ti = blockIdx.x, tj = blockIdx.y, b = blockIdx.z;
    if (tj < ti) return;
    const int i0 = ti * 128, j0 = tj * 128;
    const int wm = wid & 1, wn = wid >> 1;

    const int ab = lane >> 3;
    const int a_row = (ab & 1) * 8 + (lane & 7);
    const int a_colb = ((ab >> 1) * 8) * 2;
    const int b_row = lane & 7;
    const int b_colb = (((lane >> 3) & 1) * 8) * 2;

    const __nv_bfloat16* Xh = g_xT_hi + (size_t)b * N_ * C_;
    const __nv_bfloat16* Xl = g_xT_lo + (size_t)b * N_ * C_;

    float acc[4][4][4];
    #pragma unroll
    for (int i = 0; i < 4; i++)
        #pragma unroll
        for (int j = 0; j < 4; j++)
            #pragma unroll
            for (int q = 0; q < 4; q++) acc[i][j][q] = 0.0f;

    for (int c0 = 0; c0 < C_; c0 += 32) {
        for (int e = tid; e < 2048; e += 256) {
            int row = e >> 4, cp = e & 15;
            int gra = min(i0 + row, N_ - 1);
            int grb = min(j0 + row, N_ - 1);
            int o = row * PITCHB + cp * 4;
            *(uint32_t*)(smem + SA_H + o) = ((const uint32_t*)(Xh + (size_t)gra * C_ + c0))[cp];
            *(uint32_t*)(smem + SA_L + o) = ((const uint32_t*)(Xl + (size_t)gra * C_ + c0))[cp];
            *(uint32_t*)(smem + SB_H + o) = ((const uint32_t*)(Xh + (size_t)grb * C_ + c0))[cp];
            *(uint32_t*)(smem + SB_L + o) = ((const uint32_t*)(Xl + (size_t)grb * C_ + c0))[cp];
        }
        __syncthreads();

        #pragma unroll
        for (int ks = 0; ks < 2; ks++) {
            const int kb = ks * 32;
            uint32_t af[4][4], bfr[4][2];
            #pragma unroll
            for (int ma = 0; ma < 4; ma++)
                ldm_x4(af[ma], sb + SA_H + (wm * 64 + ma * 16 + a_row) * PITCHB + kb + a_colb);
            #pragma unroll
            for (int na = 0; na < 4; na++)
                ldm_x2(bfr[na], sb + SB_H + (wn * 32 + na * 8 + b_row) * PITCHB + kb + b_colb);
            #pragma unroll
            for (int ma = 0; ma < 4; ma++)
                #pragma unroll
                for (int na = 0; na < 4; na++) mma_bf16(acc[ma][na], af[ma], bfr[na]);
            #pragma unroll
            for (int ma = 0; ma < 4; ma++)
                ldm_x4(af[ma], sb + SA_L + (wm * 64 + ma * 16 + a_row) * PITCHB + kb + a_colb);
            #pragma unroll
            for (int ma = 0; ma < 4; ma++)
                #pragma unroll
                for (int na = 0; na < 4; na++) mma_bf16(acc[ma][na], af[ma], bfr[na]);
            #pragma unroll
            for (int ma = 0; ma < 4; ma++)
                ldm_x4(af[ma], sb + SA_H + (wm * 64 + ma * 16 + a_row) * PITCHB + kb + a_colb);
            #pragma unroll
            for (int na = 0; na < 4; na++)
                ldm_x2(bfr[na], sb + SB_L + (wn * 32 + na * 8 + b_row) * PITCHB + kb + b_colb);
            #pragma unroll
            for (int ma = 0; ma < 4; ma++)
                #pragma unroll
                for (int na = 0; na < 4; na++) mma_bf16(acc[ma][na], af[ma], bfr[na]);
        }
        __syncthreads();
    }

    // stage exp(masked E) fp32, pitch 133
    float* stg = (float*)(smem + STG);
    const bool diagblk = (ti == tj);
    #pragma unroll
    for (int ma = 0; ma < 4; ma++)
        #pragma unroll
        for (int na = 0; na < 4; na++) {
            int r0 = wm * 64 + ma * 16 + g;
            int cc = wn * 32 + na * 8 + t4 * 2;
            float d0 = acc[ma][na][0], d1 = acc[ma][na][1];
            float d2 = acc[ma][na][2], d3 = acc[ma][na][3];
            if (diagblk) {
                if (r0 == cc) d0 = 0.0f;
                if (r0 == cc + 1) d1 = 0.0f;
                if (r0 + 8 == cc) d2 = 0.0f;
                if (r0 + 8 == cc + 1) d3 = 0.0f;
            }
            stg[r0 * 133 + cc] = __expf(d0);
            stg[r0 * 133 + cc + 1] = __expf(d1);
            stg[(r0 + 8) * 133 + cc] = __expf(d2);
            stg[(r0 + 8) * 133 + cc + 1] = __expf(d3);
        }
    __syncthreads();

    const int ilim = min(128, N_ - i0), jlim = min(128, N_ - j0);

    if (tid < 128) {                      // row sums of tile ti over cols tj
        int row = tid;
        if (row < ilim) {
            float s = 0.0f;
            for (int c = 0; c < jlim; c++) s += stg[row * 133 + c];
            g_psum[((size_t)b * NT + tj) * N_ + i0 + row] = s;
        }
    } else if (ti != tj) {                // col sums = row sums of tile tj over cols ti
        int jr = tid - 128;
        if (jr < jlim) {
            float s = 0.0f;
            for (int ic = 0; ic < ilim; ic++) s += stg[ic * 133 + jr];
            g_psum[((size_t)b * NT + ti) * N_ + j0 + jr] = s;
        }
    }

    // P stores (bf16 hi/lo pairs)
    __nv_bfloat162* Ph = (__nv_bfloat162*)(g_P_hi + (size_t)b * NN);
    __nv_bfloat162* Pl = (__nv_bfloat162*)(g_P_lo + (size_t)b * NN);
    for (int e = tid; e < 8192; e += 256) {
        int r = e >> 6, cp2 = e & 63;
        if (r < ilim && 2 * cp2 < jlim) {
            float a0 = stg[r * 133 + 2 * cp2], a1 = stg[r * 133 + 2 * cp2 + 1];
            __nv_bfloat16 h0, l0, h1, l1;
            split_bf16(a0, h0, l0);
            split_bf16(a1, h1, l1);
            size_t pi = ((size_t)(i0 + r) * N_ + j0) / 2 + cp2;
            Ph[pi] = __halves2bfloat162(h0, h1);
            Pl[pi] = __halves2bfloat162(l0, l1);
        }
    }
    if (ti != tj) {
        for (int e = tid; e < 8192; e += 256) {
            int jr = e >> 6, icp = e & 63;
            if (jr < jlim && 2 * icp < ilim) {
                float a0 = stg[(2 * icp) * 133 + jr], a1 = stg[(2 * icp + 1) * 133 + jr];
                __nv_bfloat16 h0, l0, h1, l1;
                split_bf16(a0, h0, l0);
                split_bf16(a1, h1, l1);
                size_t pi = ((size_t)(j0 + jr) * N_ + i0) / 2 + icp;
                Ph[pi] = __halves2bfloat162(h0, h1);
                Pl[pi] = __halves2bfloat162(l0, l1);
            }
        }
    }
}

// ---------------------------------------------------------------------------
// K2: reduce partial sums -> inv
// ---------------------------------------------------------------------------
__global__ void k2_reduce() {
    int gidx = blockIdx.x * 256 + threadIdx.x;
    if (gidx >= B_ * N_) return;
    int b = gidx / N_, i = gidx - b * N_;
    const float* p = g_psum + (size_t)b * NT * N_ + i;
    float s = 0.0f;
    #pragma unroll
    for (int t = 0; t < NT; t++) s += p[(size_t)t * N_];
    g_inv[gidx] = 1.0f / s;
}

// ---------------------------------------------------------------------------
// K2b: V-scaled split: g_V = split(x[b][c][i] * inv[b][i])
// ---------------------------------------------------------------------------
__global__ void k2b_vscale(const float* __restrict__ x) {
    size_t idx = (size_t)blockIdx.x * 256 + threadIdx.x;
    if (idx >= XE / 2) return;
    size_t gi = idx * 2;
    int b = (int)(gi / ((size_t)C_ * N_));
    int rem = (int)(gi - (size_t)b * C_ * N_);
    int i = rem % N_;
    float2 f = ((const float2*)x)[idx];
    float2 iv = *(const float2*)&g_inv[(size_t)b * N_ + i];
    float a0 = f.x * iv.x, a1 = f.y * iv.y;
    __nv_bfloat16 h0, l0, h1, l1;
    split_bf16(a0, h0, l0);
    split_bf16(a1, h1, l1);
    ((__nv_bfloat162*)g_V_hi)[idx] = __halves2bfloat162(h0, h1);
    ((__nv_bfloat162*)g_V_lo)[idx] = __halves2bfloat162(l0, l1);
}

// ---------------------------------------------------------------------------
// K3: out[c,j] = sum_i Vs[c,i] * P[j,i]  (P symmetric, Vs = V*inv).
// Pure-copy operands via cp.async double buffering. grid (25, B), 256 thr.
// Fused relu/gamma/residual epilogue.
// ---------------------------------------------------------------------------
__device__ __forceinline__ void k3_issue(uint32_t sbuf, int tid, int iC, int j0,
                                         const __nv_bfloat16* Vh, const __nv_bfloat16* Vl,
                                         const __nv_bfloat16* Ph, const __nv_bfloat16* Pl) {
    #pragma unroll
    for (int q = 0; q < 8; q++) {
        int e = tid + q * 256;
        int tile = e >> 9, row = (e >> 2) & 127, p = e & 3;
        uint32_t dst = sbuf + tile * TILEB + row * PITCHB + p * 16;
        const __nv_bfloat16* src;
        if (tile == 0)      src = Vh + (size_t)row * N_ + iC;
        else if (tile == 1) src = Vl + (size_t)row * N_ + iC;
        else {
            int jr = min(j0 + row, N_ - 1);
            src = (tile == 2 ? Ph : Pl) + (size_t)jr * N_ + iC;
        }
        asm volatile("cp.async.cg.shared.global [%0], [%1], 16;"
                     :: "r"(dst), "l"((const char*)src + p * 16) : "memory");
    }
    asm volatile("cp.async.commit_group;" ::: "memory");
}

__global__ void __launch_bounds__(256) k3_out(const float* __restrict__ x,
                                              const float* __restrict__ gamma_p,
                                              float* __restrict__ y_out,
                                              float* __restrict__ o_out) {
    extern __shared__ char smem[];
    const uint32_t sb = smem_u32(smem);
    const int tid = threadIdx.x, wid = tid >> 5, lane = tid & 31;
    const int g = lane >> 2, t4 = lane & 3;
    const int b = blockIdx.x % B_, j0 = (blockIdx.x / B_) * 128;
    const int wm = wid & 1, wn = wid >> 1;

    const int ab = lane >> 3;
    const int a_row = (ab & 1) * 8 + (lane & 7);
    const int a_colb = ((ab >> 1) * 8) * 2;
    const int b_row = lane & 7;
    const int b_colb = (((lane >> 3) & 1) * 8) * 2;

    const __nv_bfloat16* Vh = g_V_hi + (size_t)b * C_ * N_;
    const __nv_bfloat16* Vl = g_V_lo + (size_t)b * C_ * N_;
    const __nv_bfloat16* Ph = g_P_hi + (size_t)b * NN;
    const __nv_bfloat16* Pl = g_P_lo + (size_t)b * NN;
    const float* xb = x + (size_t)b * C_ * N_;

    float acc[4][4][4];
    #pragma unroll
    for (int i = 0; i < 4; i++)
        #pragma unroll
        for (int j = 0; j < 4; j++)
            #pragma unroll
            for (int q = 0; q < 4; q++) acc[i][j][q] = 0.0f;

    k3_issue(sb, tid, 0, j0, Vh, Vl, Ph, Pl);

    for (int kc = 0; kc < 98; kc++) {
        if (kc < 97) {
            k3_issue(sb + ((kc + 1) & 1) * BUFB, tid, (kc + 1) * 32, j0, Vh, Vl, Ph, Pl);
            asm volatile("cp.async.wait_group 1;" ::: "memory");
        } else {
            asm volatile("cp.async.wait_group 0;" ::: "memory");
        }
        __syncthreads();

        const uint32_t base = sb + (kc & 1) * BUFB;
        #pragma unroll
        for (int ks = 0; ks < 2; ks++) {
            const int kb = ks * 32;
            uint32_t af[4][4], bfr[4][2];
            #pragma unroll
            for (int ma = 0; ma < 4; ma++)
                ldm_x4(af[ma], base + SA_H + (wm * 64 + ma * 16 + a_row) * PITCHB + kb + a_colb);
            #pragma unroll
            for (int na = 0; na < 4; na++)
                ldm_x2(bfr[na], base + SB_H + (wn * 32 + na * 8 + b_row) * PITCHB + kb + b_colb);
            #pragma unroll
            for (int ma = 0; ma < 4; ma++)
                #pragma unroll
                for (int na = 0; na < 4; na++) mma_bf16(acc[ma][na], af[ma], bfr[na]);
            #pragma unroll
            for (int ma = 0; ma < 4; ma++)
                ldm_x4(af[ma], base + SA_L + (wm * 64 + ma * 16 + a_row) * PITCHB + kb + a_colb);
            #pragma unroll
            for (int ma = 0; ma < 4; ma++)
                #pragma unroll
                for (int na = 0; na < 4; na++) mma_bf16(acc[ma][na], af[ma], bfr[na]);
            #pragma unroll
            for (int ma = 0; ma < 4; ma++)
                ldm_x4(af[ma], base + SA_H + (wm * 64 + ma * 16 + a_row) * PITCHB + kb + a_colb);
            #pragma unroll
            for (int na = 0; na < 4; na++)
                ldm_x2(bfr[na], base + SB_L + (wn * 32 + na * 8 + b_row) * PITCHB + kb + b_colb);
            #pragma unroll
            for (int ma = 0; ma < 4; ma++)
                #pragma unroll
                for (int na = 0; na < 4; na++) mma_bf16(acc[ma][na], af[ma], bfr[na]);
        }
        __syncthreads();
    }

    const float gamma = *gamma_p;
    #pragma unroll
    for (int ma = 0; ma < 4; ma++)
        #pragma unroll
        for (int na = 0; na < 4; na++) {
            int c = wm * 64 + ma * 16 + g;
            int j = j0 + wn * 32 + na * 8 + t4 * 2;
            if (j < N_) {
                size_t idx0 = ((size_t)b * C_ + c) * N_ + j;
                size_t idx1 = ((size_t)b * C_ + c + 8) * N_ + j;
                float o0 = fmaxf(acc[ma][na][0], 0.0f);
                float o1 = fmaxf(acc[ma][na][1], 0.0f);
                float o2 = fmaxf(acc[ma][na][2], 0.0f);
                float o3 = fmaxf(acc[ma][na][3], 0.0f);
                float2 xi0 = *(const float2*)&xb[(size_t)c * N_ + j];
                float2 xi1 = *(const float2*)&xb[(size_t)(c + 8) * N_ + j];
                *(float2*)&o_out[idx0] = make_float2(o0, o1);
                *(float2*)&o_out[idx1] = make_float2(o2, o3);
                *(float2*)&y_out[idx0] = make_float2(gamma * o0 + xi0.x, gamma * o1 + xi0.y);
                *(float2*)&y_out[idx1] = make_float2(gamma * o2 + xi1.x, gamma * o3 + xi1.y);
            }
        }
}

// ---------------------------------------------------------------------------
extern "C" void kernel_launch(void* const* d_in, const int* in_sizes, int n_in,
                              void* d_out, int out_size) {
    const float* x     = (const float*)d_in[0];
    const float* gamma = (const float*)d_in[1];
    float* out = (float*)d_out;

    float* y_sec = out;
    float* o_sec = out + XE;
    float* x_sec = out + 2 * XE;
    float* g_sec = out + 3 * XE;

    cudaFuncSetAttribute(k1_gram, cudaFuncAttributeMaxDynamicSharedMemorySize, K1_SMEM);
    cudaFuncSetAttribute(k3_out, cudaFuncAttributeMaxDynamicSharedMemorySize, K3_SMEM);

    k0_split<<<dim3(4, 98, B_), dim3(32, 8)>>>(x);
    k1_gram<<<dim3(NT, NT, B_), 256, K1_SMEM>>>();
    k2_reduce<<<(B_ * N_ + 255) / 256, 256>>>();
    k2b_vscale<<<(int)((XE / 2 + 255) / 256), 256>>>(x);
    k3_out<<<dim3(NT * B_), 256, K3_SMEM>>>(x, gamma, y_sec, o_sec);

    cudaMemcpyAsync(x_sec, x, XE * sizeof(float), cudaMemcpyDeviceToDevice);
    cudaMemcpyAsync(g_sec, gamma, sizeof(float), cudaMemcpyDeviceToDevice);
}

// round 7
// speedup vs baseline: 2.7970x; 1.1650x over previous
#include <cuda_runtime.h>
#include <cuda_bf16.h>
#include <cstdint>

static constexpr int B_ = 8;
static constexpr int C_ = 128;
static constexpr int N_ = 3136;                 // 56*56
static constexpr int NT = 25;                   // ceil(N/128)
static constexpr size_t NN = (size_t)N_ * N_;
static constexpr size_t XE = (size_t)B_ * C_ * N_;

__device__ __nv_bfloat16 g_P_hi[(size_t)B_ * NN];        // exp(E) split hi
__device__ __nv_bfloat16 g_P_lo[(size_t)B_ * NN];        // exp(E) split lo
__device__ __nv_bfloat16 g_xT_hi[(size_t)B_ * N_ * C_];  // x^T split hi  [b][n][c]
__device__ __nv_bfloat16 g_xT_lo[(size_t)B_ * N_ * C_];  // x^T split lo
__device__ __nv_bfloat16 g_V_hi[XE];                     // (x * inv) split hi [b][c][i]
__device__ __nv_bfloat16 g_V_lo[XE];
__device__ float         g_psum[(size_t)B_ * NT * N_];   // partial row sums of P
__device__ float         g_inv[(size_t)B_ * N_];         // 1 / rowsum

// ---------------------------------------------------------------------------
// helpers
// ---------------------------------------------------------------------------
__device__ __forceinline__ uint32_t smem_u32(const void* p) {
    uint32_t a;
    asm("{ .reg .u64 t; cvta.to.shared.u64 t, %1; cvt.u32.u64 %0, t; }" : "=r"(a) : "l"(p));
    return a;
}
__device__ __forceinline__ void ldm_x4(uint32_t* r, uint32_t a) {
    asm volatile("ldmatrix.sync.aligned.m8n8.x4.shared.b16 {%0,%1,%2,%3}, [%4];"
                 : "=r"(r[0]), "=r"(r[1]), "=r"(r[2]), "=r"(r[3]) : "r"(a));
}
__device__ __forceinline__ void ldm_x2(uint32_t* r, uint32_t a) {
    asm volatile("ldmatrix.sync.aligned.m8n8.x2.shared.b16 {%0,%1}, [%2];"
                 : "=r"(r[0]), "=r"(r[1]) : "r"(a));
}
__device__ __forceinline__ void mma_bf16(float* d, const uint32_t* a, const uint32_t* b) {
    asm volatile("mma.sync.aligned.m16n8k16.row.col.f32.bf16.bf16.f32 "
                 "{%0,%1,%2,%3}, {%4,%5,%6,%7}, {%8,%9}, {%0,%1,%2,%3};"
                 : "+f"(d[0]), "+f"(d[1]), "+f"(d[2]), "+f"(d[3])
                 : "r"(a[0]), "r"(a[1]), "r"(a[2]), "r"(a[3]), "r"(b[0]), "r"(b[1]));
}
__device__ __forceinline__ void split_bf16(float v, __nv_bfloat16& h, __nv_bfloat16& l) {
    h = __float2bfloat16(v);
    l = __float2bfloat16(v - __bfloat162float(h));
}

static constexpr int PITCHB = 80;               // 32 bf16 k-chunk rows, pitch 40 bf16
static constexpr int TILEB = 128 * PITCHB;      // 10240
static constexpr int SA_H = 0, SA_L = 10240, SB_H = 20480, SB_L = 30720;
static constexpr int BUFB = 40960;
static constexpr int K1_SMEM = 2 * BUFB;        // stage (68096B) reuses buffers post-loop
static constexpr int K3_SMEM = 2 * BUFB;        // 81920

// ---------------------------------------------------------------------------
// K0: split/transpose x -> xT_hi/lo [b][n][c]
// ---------------------------------------------------------------------------
__global__ void k0_split(const float* __restrict__ x) {
    __shared__ float t[32][33];
    const int b = blockIdx.z, c0 = blockIdx.x * 32, n0 = blockIdx.y * 32;
    const int tx = threadIdx.x, ty = threadIdx.y;   // 32 x 8
    const float* xb = x + (size_t)b * C_ * N_;
    #pragma unroll
    for (int r = 0; r < 4; r++) {
        int c = ty + r * 8;
        t[c][tx] = xb[(size_t)(c0 + c) * N_ + n0 + tx];
    }
    __syncthreads();
    __nv_bfloat16* Th = g_xT_hi + (size_t)b * N_ * C_;
    __nv_bfloat16* Tl = g_xT_lo + (size_t)b * N_ * C_;
    #pragma unroll
    for (int r = 0; r < 4; r++) {
        int n = ty + r * 8;
        float v = t[tx][n];
        __nv_bfloat16 h, l;
        split_bf16(v, h, l);
        size_t o = (size_t)(n0 + n) * C_ + c0 + tx;
        Th[o] = h; Tl[o] = l;
    }
}

// ---------------------------------------------------------------------------
// MMA inner step shared by k1/k3: reuse-ordered 3 passes over one 32-k chunk
// buffer (Ah,Bh) -> (Ah,Bl) -> (Al,Bh).
// ---------------------------------------------------------------------------
__device__ __forceinline__ void mma_chunk(float acc[4][4][4], uint32_t base,
                                          int wm, int wn, int a_row, int a_colb,
                                          int b_row, int b_colb) {
    #pragma unroll
    for (int ks = 0; ks < 2; ks++) {
        const int kb = ks * 32;
        uint32_t ah[4][4], al[4][4], bh[4][2], bl[4][2];
        #pragma unroll
        for (int ma = 0; ma < 4; ma++)
            ldm_x4(ah[ma], base + SA_H + (wm * 64 + ma * 16 + a_row) * PITCHB + kb + a_colb);
        #pragma unroll
        for (int na = 0; na < 4; na++)
            ldm_x2(bh[na], base + SB_H + (wn * 32 + na * 8 + b_row) * PITCHB + kb + b_colb);
        #pragma unroll
        for (int ma = 0; ma < 4; ma++)
            #pragma unroll
            for (int na = 0; na < 4; na++) mma_bf16(acc[ma][na], ah[ma], bh[na]);
        #pragma unroll
        for (int na = 0; na < 4; na++)
            ldm_x2(bl[na], base + SB_L + (wn * 32 + na * 8 + b_row) * PITCHB + kb + b_colb);
        #pragma unroll
        for (int ma = 0; ma < 4; ma++)
            #pragma unroll
            for (int na = 0; na < 4; na++) mma_bf16(acc[ma][na], ah[ma], bl[na]);
        #pragma unroll
        for (int ma = 0; ma < 4; ma++)
            ldm_x4(al[ma], base + SA_L + (wm * 64 + ma * 16 + a_row) * PITCHB + kb + a_colb);
        #pragma unroll
        for (int ma = 0; ma < 4; ma++)
            #pragma unroll
            for (int na = 0; na < 4; na++) mma_bf16(acc[ma][na], al[ma], bh[na]);
    }
}

// ---------------------------------------------------------------------------
// K1: P-tile = exp(mask(xT * xT^T)), symmetry tj>=ti, cp.async double buffer.
// grid (25, 25, B), 256 threads (8 warps 2m x 4n, warp tile 64x32).
// ---------------------------------------------------------------------------
__device__ __forceinline__ void k1_issue(uint32_t sbuf, int tid, int c0, int i0, int j0,
                                         const __nv_bfloat16* Xh, const __nv_bfloat16* Xl) {
    #pragma unroll
    for (int q = 0; q < 8; q++) {
        int e = tid + q * 256;
        int tile = e >> 9, row = (e >> 2) & 127, p = e & 3;
        int gr = min(((tile < 2) ? i0 : j0) + row, N_ - 1);
        const __nv_bfloat16* src = ((tile & 1) ? Xl : Xh) + (size_t)gr * C_ + c0;
        uint32_t dst = sbuf + tile * TILEB + row * PITCHB + p * 16;
        asm volatile("cp.async.cg.shared.global [%0], [%1], 16;"
                     :: "r"(dst), "l"((const char*)src + p * 16) : "memory");
    }
    asm volatile("cp.async.commit_group;" ::: "memory");
}

__global__ void __launch_bounds__(256, 2) k1_gram() {
    extern __shared__ char smem[];
    const uint32_t sb = smem_u32(smem);
    const int tid = threadIdx.x, wid = tid >> 5, lane = tid & 31;
    const int g = lane >> 2, t4 = lane & 3;
    const int ti = blockIdx.x, tj = blockIdx.y, b = blockIdx.z;
    if (tj < ti) return;
    const int i0 = ti * 128, j0 = tj * 128;
    const int wm = wid & 1, wn = wid >> 1;

    const int ab = lane >> 3;
    const int a_row = (ab & 1) * 8 + (lane & 7);
    const int a_colb = ((ab >> 1) * 8) * 2;
    const int b_row = lane & 7;
    const int b_colb = (((lane >> 3) & 1) * 8) * 2;

    const __nv_bfloat16* Xh = g_xT_hi + (size_t)b * N_ * C_;
    const __nv_bfloat16* Xl = g_xT_lo + (size_t)b * N_ * C_;

    float acc[4][4][4];
    #pragma unroll
    for (int i = 0; i < 4; i++)
        #pragma unroll
        for (int j = 0; j < 4; j++)
            #pragma unroll
            for (int q = 0; q < 4; q++) acc[i][j][q] = 0.0f;

    k1_issue(sb, tid, 0, i0, j0, Xh, Xl);
    #pragma unroll
    for (int kc = 0; kc < 4; kc++) {
        if (kc < 3) {
            k1_issue(sb + ((kc + 1) & 1) * BUFB, tid, (kc + 1) * 32, i0, j0, Xh, Xl);
            asm volatile("cp.async.wait_group 1;" ::: "memory");
        } else {
            asm volatile("cp.async.wait_group 0;" ::: "memory");
        }
        __syncthreads();
        mma_chunk(acc, sb + (kc & 1) * BUFB, wm, wn, a_row, a_colb, b_row, b_colb);
        __syncthreads();
    }

    // stage exp(masked E) fp32, pitch 133 (reuses buffer smem)
    float* stg = (float*)smem;
    const bool diagblk = (ti == tj);
    #pragma unroll
    for (int ma = 0; ma < 4; ma++)
        #pragma unroll
        for (int na = 0; na < 4; na++) {
            int r0 = wm * 64 + ma * 16 + g;
            int cc = wn * 32 + na * 8 + t4 * 2;
            float d0 = acc[ma][na][0], d1 = acc[ma][na][1];
            float d2 = acc[ma][na][2], d3 = acc[ma][na][3];
            if (diagblk) {
                if (r0 == cc) d0 = 0.0f;
                if (r0 == cc + 1) d1 = 0.0f;
                if (r0 + 8 == cc) d2 = 0.0f;
                if (r0 + 8 == cc + 1) d3 = 0.0f;
            }
            stg[r0 * 133 + cc] = __expf(d0);
            stg[r0 * 133 + cc + 1] = __expf(d1);
            stg[(r0 + 8) * 133 + cc] = __expf(d2);
            stg[(r0 + 8) * 133 + cc + 1] = __expf(d3);
        }
    __syncthreads();

    const int ilim = min(128, N_ - i0), jlim = min(128, N_ - j0);

    if (tid < 128) {
        int row = tid;
        if (row < ilim) {
            float s = 0.0f;
            for (int c = 0; c < jlim; c++) s += stg[row * 133 + c];
            g_psum[((size_t)b * NT + tj) * N_ + i0 + row] = s;
        }
    } else if (ti != tj) {
        int jr = tid - 128;
        if (jr < jlim) {
            float s = 0.0f;
            for (int ic = 0; ic < ilim; ic++) s += stg[ic * 133 + jr];
            g_psum[((size_t)b * NT + ti) * N_ + j0 + jr] = s;
        }
    }

    __nv_bfloat162* Ph = (__nv_bfloat162*)(g_P_hi + (size_t)b * NN);
    __nv_bfloat162* Pl = (__nv_bfloat162*)(g_P_lo + (size_t)b * NN);
    for (int e = tid; e < 8192; e += 256) {
        int r = e >> 6, cp2 = e & 63;
        if (r < ilim && 2 * cp2 < jlim) {
            float a0 = stg[r * 133 + 2 * cp2], a1 = stg[r * 133 + 2 * cp2 + 1];
            __nv_bfloat16 h0, l0, h1, l1;
            split_bf16(a0, h0, l0);
            split_bf16(a1, h1, l1);
            size_t pi = ((size_t)(i0 + r) * N_ + j0) / 2 + cp2;
            Ph[pi] = __halves2bfloat162(h0, h1);
            Pl[pi] = __halves2bfloat162(l0, l1);
        }
    }
    if (ti != tj) {
        for (int e = tid; e < 8192; e += 256) {
            int jr = e >> 6, icp = e & 63;
            if (jr < jlim && 2 * icp < ilim) {
                float a0 = stg[(2 * icp) * 133 + jr], a1 = stg[(2 * icp + 1) * 133 + jr];
                __nv_bfloat16 h0, l0, h1, l1;
                split_bf16(a0, h0, l0);
                split_bf16(a1, h1, l1);
                size_t pi = ((size_t)(j0 + jr) * N_ + i0) / 2 + icp;
                Ph[pi] = __halves2bfloat162(h0, h1);
                Pl[pi] = __halves2bfloat162(l0, l1);
            }
        }
    }
}

// ---------------------------------------------------------------------------
// K2: reduce partial sums -> inv
// ---------------------------------------------------------------------------
__global__ void k2_reduce() {
    int gidx = blockIdx.x * 256 + threadIdx.x;
    if (gidx >= B_ * N_) return;
    int b = gidx / N_, i = gidx - b * N_;
    const float* p = g_psum + (size_t)b * NT * N_ + i;
    float s = 0.0f;
    #pragma unroll
    for (int t = 0; t < NT; t++) s += p[(size_t)t * N_];
    g_inv[gidx] = 1.0f / s;
}

// ---------------------------------------------------------------------------
// K2b: V-scaled split: g_V = split(x[b][c][i] * inv[b][i])
// ---------------------------------------------------------------------------
__global__ void k2b_vscale(const float* __restrict__ x) {
    size_t idx = (size_t)blockIdx.x * 256 + threadIdx.x;
    if (idx >= XE / 2) return;
    size_t gi = idx * 2;
    int b = (int)(gi / ((size_t)C_ * N_));
    int rem = (int)(gi - (size_t)b * C_ * N_);
    int i = rem % N_;
    float2 f = ((const float2*)x)[idx];
    float2 iv = *(const float2*)&g_inv[(size_t)b * N_ + i];
    float a0 = f.x * iv.x, a1 = f.y * iv.y;
    __nv_bfloat16 h0, l0, h1, l1;
    split_bf16(a0, h0, l0);
    split_bf16(a1, h1, l1);
    ((__nv_bfloat162*)g_V_hi)[idx] = __halves2bfloat162(h0, h1);
    ((__nv_bfloat162*)g_V_lo)[idx] = __halves2bfloat162(l0, l1);
}

// ---------------------------------------------------------------------------
// K3: out[c,j] = sum_i Vs[c,i] * P[j,i]  (P symmetric, Vs = V*inv).
// Pure-copy operands via cp.async double buffering. Fused epilogue.
// ---------------------------------------------------------------------------
__device__ __forceinline__ void k3_issue(uint32_t sbuf, int tid, int iC, int j0,
                                         const __nv_bfloat16* Vh, const __nv_bfloat16* Vl,
                                         const __nv_bfloat16* Ph, const __nv_bfloat16* Pl) {
    #pragma unroll
    for (int q = 0; q < 8; q++) {
        int e = tid + q * 256;
        int tile = e >> 9, row = (e >> 2) & 127, p = e & 3;
        uint32_t dst = sbuf + tile * TILEB + row * PITCHB + p * 16;
        const __nv_bfloat16* src;
        if (tile == 0)      src = Vh + (size_t)row * N_ + iC;
        else if (tile == 1) src = Vl + (size_t)row * N_ + iC;
        else {
            int jr = min(j0 + row, N_ - 1);
            src = (tile == 2 ? Ph : Pl) + (size_t)jr * N_ + iC;
        }
        asm volatile("cp.async.cg.shared.global [%0], [%1], 16;"
                     :: "r"(dst), "l"((const char*)src + p * 16) : "memory");
    }
    asm volatile("cp.async.commit_group;" ::: "memory");
}

__global__ void __launch_bounds__(256, 2) k3_out(const float* __restrict__ x,
                                                 const float* __restrict__ gamma_p,
                                                 float* __restrict__ y_out,
                                                 float* __restrict__ o_out) {
    extern __shared__ char smem[];
    const uint32_t sb = smem_u32(smem);
    const int tid = threadIdx.x, wid = tid >> 5, lane = tid & 31;
    const int g = lane >> 2, t4 = lane & 3;
    const int b = blockIdx.x % B_, j0 = (blockIdx.x / B_) * 128;
    const int wm = wid & 1, wn = wid >> 1;

    const int ab = lane >> 3;
    const int a_row = (ab & 1) * 8 + (lane & 7);
    const int a_colb = ((ab >> 1) * 8) * 2;
    const int b_row = lane & 7;
    const int b_colb = (((lane >> 3) & 1) * 8) * 2;

    const __nv_bfloat16* Vh = g_V_hi + (size_t)b * C_ * N_;
    const __nv_bfloat16* Vl = g_V_lo + (size_t)b * C_ * N_;
    const __nv_bfloat16* Ph = g_P_hi + (size_t)b * NN;
    const __nv_bfloat16* Pl = g_P_lo + (size_t)b * NN;
    const float* xb = x + (size_t)b * C_ * N_;

    float acc[4][4][4];
    #pragma unroll
    for (int i = 0; i < 4; i++)
        #pragma unroll
        for (int j = 0; j < 4; j++)
            #pragma unroll
            for (int q = 0; q < 4; q++) acc[i][j][q] = 0.0f;

    k3_issue(sb, tid, 0, j0, Vh, Vl, Ph, Pl);

    for (int kc = 0; kc < 98; kc++) {
        if (kc < 97) {
            k3_issue(sb + ((kc + 1) & 1) * BUFB, tid, (kc + 1) * 32, j0, Vh, Vl, Ph, Pl);
            asm volatile("cp.async.wait_group 1;" ::: "memory");
        } else {
            asm volatile("cp.async.wait_group 0;" ::: "memory");
        }
        __syncthreads();
        mma_chunk(acc, sb + (kc & 1) * BUFB, wm, wn, a_row, a_colb, b_row, b_colb);
        __syncthreads();
    }

    const float gamma = *gamma_p;
    #pragma unroll
    for (int ma = 0; ma < 4; ma++)
        #pragma unroll
        for (int na = 0; na < 4; na++) {
            int c = wm * 64 + ma * 16 + g;
            int j = j0 + wn * 32 + na * 8 + t4 * 2;
            if (j < N_) {
                size_t idx0 = ((size_t)b * C_ + c) * N_ + j;
                size_t idx1 = ((size_t)b * C_ + c + 8) * N_ + j;
                float o0 = fmaxf(acc[ma][na][0], 0.0f);
                float o1 = fmaxf(acc[ma][na][1], 0.0f);
                float o2 = fmaxf(acc[ma][na][2], 0.0f);
                float o3 = fmaxf(acc[ma][na][3], 0.0f);
                float2 xi0 = *(const float2*)&xb[(size_t)c * N_ + j];
                float2 xi1 = *(const float2*)&xb[(size_t)(c + 8) * N_ + j];
                *(float2*)&o_out[idx0] = make_float2(o0, o1);
                *(float2*)&o_out[idx1] = make_float2(o2, o3);
                *(float2*)&y_out[idx0] = make_float2(gamma * o0 + xi0.x, gamma * o1 + xi0.y);
                *(float2*)&y_out[idx1] = make_float2(gamma * o2 + xi1.x, gamma * o3 + xi1.y);
            }
        }
}

// ---------------------------------------------------------------------------
extern "C" void kernel_launch(void* const* d_in, const int* in_sizes, int n_in,
                              void* d_out, int out_size) {
    const float* x     = (const float*)d_in[0];
    const float* gamma = (const float*)d_in[1];
    float* out = (float*)d_out;

    float* y_sec = out;
    float* o_sec = out + XE;
    float* x_sec = out + 2 * XE;
    float* g_sec = out + 3 * XE;

    cudaFuncSetAttribute(k1_gram, cudaFuncAttributeMaxDynamicSharedMemorySize, K1_SMEM);
    cudaFuncSetAttribute(k3_out, cudaFuncAttributeMaxDynamicSharedMemorySize, K3_SMEM);

    k0_split<<<dim3(4, 98, B_), dim3(32, 8)>>>(x);
    k1_gram<<<dim3(NT, NT, B_), 256, K1_SMEM>>>();
    k2_reduce<<<(B_ * N_ + 255) / 256, 256>>>();
    k2b_vscale<<<(int)((XE / 2 + 255) / 256), 256>>>(x);
    k3_out<<<dim3(NT * B_), 256, K3_SMEM>>>(x, gamma, y_sec, o_sec);

    cudaMemcpyAsync(x_sec, x, XE * sizeof(float), cudaMemcpyDeviceToDevice);
    cudaMemcpyAsync(g_sec, gamma, sizeof(float), cudaMemcpyDeviceToDevice);
}